// round 2
// baseline (speedup 1.0000x reference)
#include <cuda_runtime.h>

typedef unsigned long long ull;

#define N_NODES 100000
#define N_EDGES 1600000
#define HID 64
#define EDIM 16
#define IN1 144   // 2*HID + EDIM

// scatter-add scratch (static device global: allocation-free)
__device__ float g_agg[(size_t)N_NODES * HID];

// ---------- packed f32x2 helpers ----------
__device__ __forceinline__ ull pack2(float v) {
    ull r;
    asm("mov.b64 %0, {%1, %1};" : "=l"(r) : "f"(v));
    return r;
}
__device__ __forceinline__ void unpack2(ull v, float& lo, float& hi) {
    asm("mov.b64 {%0, %1}, %2;" : "=f"(lo), "=f"(hi) : "l"(v));
}
__device__ __forceinline__ void ffma2(ull& d, ull a, ull b) {
    asm("fma.rn.f32x2 %0, %1, %2, %0;" : "+l"(d) : "l"(a), "l"(b));
}
__device__ __forceinline__ float silu_f(float v) {
    return __fdividef(v, 1.0f + __expf(-v));
}
__device__ __forceinline__ void red_add4(float* p, float a, float b, float c, float d) {
    asm volatile("red.global.add.v4.f32 [%0], {%1, %2, %3, %4};"
                 :: "l"(p), "f"(a), "f"(b), "f"(c), "f"(d) : "memory");
}

// accumulate one input value against one 64-wide weight row (32 packed FMAs)
__device__ __forceinline__ void accum1(ull* acc, ull m, const float* row) {
    const ulonglong2* r = (const ulonglong2*)row;
    #pragma unroll
    for (int j = 0; j < 16; j++) {
        ulonglong2 w = r[j];           // broadcast LDS.128 (all lanes same addr)
        ffma2(acc[2 * j],     m, w.x);
        ffma2(acc[2 * j + 1], m, w.y);
    }
}
__device__ __forceinline__ void accum4(ull* acc, float4 v, const float* base) {
    accum1(acc, pack2(v.x), base);
    accum1(acc, pack2(v.y), base + HID);
    accum1(acc, pack2(v.z), base + 2 * HID);
    accum1(acc, pack2(v.w), base + 3 * HID);
}

// ---------- zero the aggregation buffer ----------
__global__ void zero_agg_kernel() {
    size_t i = (size_t)blockIdx.x * blockDim.x + threadIdx.x;
    size_t n = (size_t)N_NODES * HID / 4;
    if (i < n) ((float4*)g_agg)[i] = make_float4(0.f, 0.f, 0.f, 0.f);
}

// ---------- edge MLP + scatter ----------
#define EDGE_SMEM ((IN1 * HID + HID * HID + 2 * HID) * 4)  // 53760 B

__global__ void __launch_bounds__(128, 3) edge_kernel(
    const float* __restrict__ x, const int* __restrict__ ei,
    const float* __restrict__ ea,
    const float* __restrict__ W1, const float* __restrict__ b1,
    const float* __restrict__ W2, const float* __restrict__ b2)
{
    extern __shared__ float sm[];
    float* sW1 = sm;                          // 144*64
    float* sW2 = sm + IN1 * HID;              // 64*64
    float* sB1 = sm + IN1 * HID + HID * HID;  // 64
    float* sB2 = sB1 + HID;                   // 64

    for (int i = threadIdx.x; i < IN1 * HID / 4; i += blockDim.x)
        ((float4*)sW1)[i] = __ldg(((const float4*)W1) + i);
    for (int i = threadIdx.x; i < HID * HID / 4; i += blockDim.x)
        ((float4*)sW2)[i] = __ldg(((const float4*)W2) + i);
    if (threadIdx.x < HID)            sB1[threadIdx.x]       = b1[threadIdx.x];
    else if (threadIdx.x < 2 * HID)   sB2[threadIdx.x - HID] = b2[threadIdx.x - HID];
    __syncthreads();

    const int* srcp = ei;
    const int* dstp = ei + N_EDGES;

    for (int e = blockIdx.x * blockDim.x + threadIdx.x; e < N_EDGES;
         e += gridDim.x * blockDim.x) {
        int s = srcp[e], d = dstp[e];
        const float4* xs  = (const float4*)(x  + (size_t)s * HID);
        const float4* xd  = (const float4*)(x  + (size_t)d * HID);
        const float4* eap = (const float4*)(ea + (size_t)e * EDIM);

        // ---- layer 1: h_pre = W1^T m_in + b1 (packed pairs) ----
        ull acc[HID / 2];
        #pragma unroll
        for (int j = 0; j < HID / 2; j++) acc[j] = ((const ull*)sB1)[j];

        #pragma unroll 1
        for (int k4 = 0; k4 < 16; k4++)
            accum4(acc, xs[k4], sW1 + (4 * k4) * HID);
        #pragma unroll 1
        for (int k4 = 0; k4 < 16; k4++)
            accum4(acc, xd[k4], sW1 + (64 + 4 * k4) * HID);
        #pragma unroll 1
        for (int k4 = 0; k4 < 4; k4++)
            accum4(acc, eap[k4], sW1 + (128 + 4 * k4) * HID);

        // ---- layer 2: msg_pre = W2^T silu(h_pre) + b2 ----
        ull acc2[HID / 2];
        #pragma unroll
        for (int j = 0; j < HID / 2; j++) acc2[j] = ((const ull*)sB2)[j];

        #pragma unroll
        for (int kp = 0; kp < HID / 2; kp++) {
            float lo, hi;
            unpack2(acc[kp], lo, hi);
            accum1(acc2, pack2(silu_f(lo)), sW2 + (2 * kp) * HID);
            accum1(acc2, pack2(silu_f(hi)), sW2 + (2 * kp + 1) * HID);
        }

        // ---- silu + vectorized scatter-add onto dst node ----
        float* aggp = g_agg + (size_t)d * HID;
        #pragma unroll
        for (int j = 0; j < 16; j++) {
            float a0, a1, a2, a3;
            unpack2(acc2[2 * j],     a0, a1);
            unpack2(acc2[2 * j + 1], a2, a3);
            red_add4(aggp + 4 * j, silu_f(a0), silu_f(a1), silu_f(a2), silu_f(a3));
        }
    }
}

// ---------- node MLP ----------
#define NODE_SMEM ((2 * HID * HID + HID) * 4)  // 33024 B

__global__ void __launch_bounds__(128) node_kernel(
    const float* __restrict__ x,
    const float* __restrict__ W3, const float* __restrict__ b3,
    float* __restrict__ out)
{
    extern __shared__ float sm[];
    float* sW3 = sm;                 // 128*64
    float* sB3 = sm + 2 * HID * HID; // 64

    for (int i = threadIdx.x; i < 2 * HID * HID / 4; i += blockDim.x)
        ((float4*)sW3)[i] = __ldg(((const float4*)W3) + i);
    if (threadIdx.x < HID) sB3[threadIdx.x] = b3[threadIdx.x];
    __syncthreads();

    int n = blockIdx.x * blockDim.x + threadIdx.x;
    if (n >= N_NODES) return;

    const float4* xr = (const float4*)(x     + (size_t)n * HID);
    const float4* ar = (const float4*)(g_agg + (size_t)n * HID);

    ull acc[HID / 2];
    #pragma unroll
    for (int j = 0; j < HID / 2; j++) acc[j] = ((const ull*)sB3)[j];

    #pragma unroll 1
    for (int k4 = 0; k4 < 16; k4++)
        accum4(acc, xr[k4], sW3 + (4 * k4) * HID);
    #pragma unroll 1
    for (int k4 = 0; k4 < 16; k4++)
        accum4(acc, ar[k4], sW3 + (64 + 4 * k4) * HID);

    float4* op = (float4*)(out + (size_t)n * HID);
    #pragma unroll
    for (int j = 0; j < 16; j++) {
        float a0, a1, a2, a3;
        unpack2(acc[2 * j],     a0, a1);
        unpack2(acc[2 * j + 1], a2, a3);
        op[j] = make_float4(silu_f(a0), silu_f(a1), silu_f(a2), silu_f(a3));
    }
}

extern "C" void kernel_launch(void* const* d_in, const int* in_sizes, int n_in,
                              void* d_out, int out_size) {
    const float* x   = (const float*)d_in[0];
    const int*   ei  = (const int*)  d_in[1];
    const float* ea  = (const float*)d_in[2];
    const float* W1  = (const float*)d_in[3];
    const float* b1  = (const float*)d_in[4];
    const float* W2  = (const float*)d_in[5];
    const float* b2  = (const float*)d_in[6];
    const float* W3  = (const float*)d_in[7];
    const float* b3  = (const float*)d_in[8];
    float* out = (float*)d_out;

    // opt-in >48KB dynamic smem (idempotent, capture-safe: no stream work)
    cudaFuncSetAttribute(edge_kernel, cudaFuncAttributeMaxDynamicSharedMemorySize, EDGE_SMEM);
    cudaFuncSetAttribute(node_kernel, cudaFuncAttributeMaxDynamicSharedMemorySize, NODE_SMEM);

    int zgrid = (N_NODES * HID / 4 + 255) / 256;
    zero_agg_kernel<<<zgrid, 256>>>();

    edge_kernel<<<444, 128, EDGE_SMEM>>>(x, ei, ea, W1, b1, W2, b2);

    int ngrid = (N_NODES + 127) / 128;
    node_kernel<<<ngrid, 128, NODE_SMEM>>>(x, W3, b3, out);
}